// round 4
// baseline (speedup 1.0000x reference)
#include <cuda_runtime.h>
#include <cstdint>
#include <cstring>
#include <vector>
#include <algorithm>

#define B_ROWS 16384
#define D_COLS 2048
#define NCLS   1000

// Scratch (device globals: allocation-free per harness rules)
__device__ unsigned short g_index[B_ROWS];          // permutation, host-computed
__device__ unsigned short g_rows[B_ROWS];           // row ids grouped by class (CSR)
__device__ int g_off[NCLS + 1];                     // CSR offsets
__device__ float g_cn[NCLS * D_COLS];               // class_noise matrix (8MB)

// ---------------------------------------------------------------------------
// JAX threefry2x32 (20 rounds), bit-exact. Host+device.
// ---------------------------------------------------------------------------
__host__ __device__ __forceinline__ void threefry2x32(
    uint32_t k0, uint32_t k1, uint32_t x0, uint32_t x1,
    uint32_t &o0, uint32_t &o1)
{
    uint32_t ks0 = k0, ks1 = k1, ks2 = k0 ^ k1 ^ 0x1BD11BDAu;
    x0 += ks0; x1 += ks1;
    const int R[2][4] = {{13, 15, 26, 6}, {17, 29, 16, 24}};
#pragma unroll
    for (int i = 0; i < 5; i++) {
#pragma unroll
        for (int j = 0; j < 4; j++) {
            int r = R[i & 1][j];
            x0 += x1;
            x1 = (x1 << r) | (x1 >> (32 - r));
            x1 ^= x0;
        }
        uint32_t a = (i + 1) % 3 == 0 ? ks0 : ((i + 1) % 3 == 1 ? ks1 : ks2);
        uint32_t b = (i + 2) % 3 == 0 ? ks0 : ((i + 2) % 3 == 1 ? ks1 : ks2);
        x0 += a;
        x1 += b + (uint32_t)(i + 1);
    }
    o0 = x0; o1 = x1;
}

// ---------------------------------------------------------------------------
// XLA f32 ErfInv (Giles polynomial)
// ---------------------------------------------------------------------------
__device__ __forceinline__ float erfinv_f32(float x)
{
    float w = -log1pf(-x * x);
    float p;
    if (w < 5.0f) {
        w -= 2.5f;
        p = 2.81022636e-08f;
        p = fmaf(p, w, 3.43273939e-07f);
        p = fmaf(p, w, -3.5233877e-06f);
        p = fmaf(p, w, -4.39150654e-06f);
        p = fmaf(p, w, 0.00021858087f);
        p = fmaf(p, w, -0.00125372503f);
        p = fmaf(p, w, -0.00417768164f);
        p = fmaf(p, w, 0.246640727f);
        p = fmaf(p, w, 1.50140941f);
    } else {
        w = sqrtf(w) - 3.0f;
        p = -0.000200214257f;
        p = fmaf(p, w, 0.000100950558f);
        p = fmaf(p, w, 0.00134934322f);
        p = fmaf(p, w, -0.00367342844f);
        p = fmaf(p, w, 0.00573950773f);
        p = fmaf(p, w, -0.0076224613f);
        p = fmaf(p, w, 0.00943887047f);
        p = fmaf(p, w, 1.00167406f);
        p = fmaf(p, w, 2.83297682f);
    }
    return p * x;
}

__device__ __forceinline__ float jax_normal(uint32_t nk0, uint32_t nk1, uint32_t idx)
{
    uint32_t b0, b1;
    threefry2x32(nk0, nk1, 0u, idx, b0, b1);
    uint32_t bits = b0 ^ b1;
    float f = __uint_as_float((bits >> 9) | 0x3f800000u);   // [1,2)
    const float lo = -0.99999994039535522461f;               // nextafter(-1,0)
    float u = fmaxf(lo, fmaf(f - 1.0f, 2.0f, lo));
    return 1.41421356237309504880f * erfinv_f32(u);
}

__device__ __forceinline__ float cn_val(float s, float q, float cnt,
                                        uint32_t nk0, uint32_t nk1, uint32_t flat)
{
    float mean = s / cnt;
    float var  = (q - cnt * mean * mean) / (cnt - 1.0f);
    float sd   = sqrtf(fmaxf(var, 0.0f));
    return mean + sd * jax_normal(nk0, nk1, flat);
}

// ---------------------------------------------------------------------------
// Kernel A: build per-class CSR of row indices (single CTA, 1024 threads).
// histogram -> Hillis-Steele scan -> scatter -> per-class insertion sort
// (1 thread/class) for a deterministic, sorted accumulation order.
// ---------------------------------------------------------------------------
__global__ __launch_bounds__(1024) void build_csr_kernel(const int* __restrict__ y)
{
    __shared__ int cnt[1024];
    __shared__ int sc[1024];
    __shared__ int cur[1024];
    int t = threadIdx.x;
    cnt[t] = 0;
    __syncthreads();
    for (int i = t; i < B_ROWS; i += 1024) atomicAdd(&cnt[y[i]], 1);
    __syncthreads();
    sc[t] = cnt[t];
    __syncthreads();
    for (int d = 1; d < 1024; d <<= 1) {
        int add = (t >= d) ? sc[t - d] : 0;
        __syncthreads();
        sc[t] += add;
        __syncthreads();
    }
    int excl = (t == 0) ? 0 : sc[t - 1];   // exclusive prefix
    cur[t] = excl;
    if (t <= NCLS) g_off[t] = (t == 0) ? 0 : sc[t - 1];
    __syncthreads();
    for (int i = t; i < B_ROWS; i += 1024) {
        int c = y[i];
        int p = atomicAdd(&cur[c], 1);
        g_rows[p] = (unsigned short)i;
    }
    __syncthreads();
    if (t < NCLS) {   // sort each class segment ascending (deterministic order)
        int s = excl, e = sc[t];
        for (int a = s + 1; a < e; a++) {
            unsigned short v = g_rows[a];
            int b = a - 1;
            while (b >= s && g_rows[b] > v) { g_rows[b + 1] = g_rows[b]; b--; }
            g_rows[b + 1] = v;
        }
    }
}

// ---------------------------------------------------------------------------
// Kernel B: per-class stats fused with noise generation.
// grid (NCLS, 4): one CTA per (class, 512-float D-chunk); 128 thr x 1 float4.
// Row loop unrolled x4 -> 4 independent LDG.128 in flight per thread.
// ---------------------------------------------------------------------------
__global__ __launch_bounds__(128) void stats_noise_kernel(
    const float* __restrict__ x, uint32_t nk0, uint32_t nk1)
{
    __shared__ unsigned short rows[256];
    int c = blockIdx.x;
    int t = threadIdx.x;
    int beg = __ldg(&g_off[c]);
    int n   = __ldg(&g_off[c + 1]) - beg;
    for (int i = t; i < n && i < 256; i += 128) rows[i] = g_rows[beg + i];
    __syncthreads();

    int col = blockIdx.y * 512 + t * 4;                 // float index in row
    const float* xb = x + col;
    float4 s = {0, 0, 0, 0}, q = {0, 0, 0, 0};

    int r = 0;
    for (; r + 4 <= n; r += 4) {
        size_t r0 = rows[r], r1 = rows[r + 1], r2 = rows[r + 2], r3 = rows[r + 3];
        float4 v0 = __ldcs(reinterpret_cast<const float4*>(xb + r0 * D_COLS));
        float4 v1 = __ldcs(reinterpret_cast<const float4*>(xb + r1 * D_COLS));
        float4 v2 = __ldcs(reinterpret_cast<const float4*>(xb + r2 * D_COLS));
        float4 v3 = __ldcs(reinterpret_cast<const float4*>(xb + r3 * D_COLS));
        s.x += v0.x; s.y += v0.y; s.z += v0.z; s.w += v0.w;
        q.x += v0.x*v0.x; q.y += v0.y*v0.y; q.z += v0.z*v0.z; q.w += v0.w*v0.w;
        s.x += v1.x; s.y += v1.y; s.z += v1.z; s.w += v1.w;
        q.x += v1.x*v1.x; q.y += v1.y*v1.y; q.z += v1.z*v1.z; q.w += v1.w*v1.w;
        s.x += v2.x; s.y += v2.y; s.z += v2.z; s.w += v2.w;
        q.x += v2.x*v2.x; q.y += v2.y*v2.y; q.z += v2.z*v2.z; q.w += v2.w*v2.w;
        s.x += v3.x; s.y += v3.y; s.z += v3.z; s.w += v3.w;
        q.x += v3.x*v3.x; q.y += v3.y*v3.y; q.z += v3.z*v3.z; q.w += v3.w*v3.w;
    }
    for (; r < n; r++) {
        size_t rr = (r < 256) ? (size_t)rows[r] : (size_t)g_rows[beg + r];
        float4 v = __ldcs(reinterpret_cast<const float4*>(xb + rr * D_COLS));
        s.x += v.x; s.y += v.y; s.z += v.z; s.w += v.w;
        q.x += v.x*v.x; q.y += v.y*v.y; q.z += v.z*v.z; q.w += v.w*v.w;
    }

    float cnt = (float)n;
    uint32_t flat = (uint32_t)c * (uint32_t)D_COLS + (uint32_t)col;
    float4 o;
    o.x = cn_val(s.x, q.x, cnt, nk0, nk1, flat + 0u);
    o.y = cn_val(s.y, q.y, cnt, nk0, nk1, flat + 1u);
    o.z = cn_val(s.z, q.z, cnt, nk0, nk1, flat + 2u);
    o.w = cn_val(s.w, q.w, cnt, nk0, nk1, flat + 3u);
    *reinterpret_cast<float4*>(g_cn + (size_t)c * D_COLS + col) = o;
}

// ---------------------------------------------------------------------------
// Kernel C: out = 0.9*x + 0.1*cn[newY[row]], newY[row] = y[perm[row]]
// Front-batched loads (MLP_p1=4); streaming hints keep g_cn L2-resident.
// ---------------------------------------------------------------------------
__global__ __launch_bounds__(256) void out_kernel(
    const float* __restrict__ x, const int* __restrict__ y,
    float* __restrict__ out, int out_size)
{
    int row = blockIdx.x;
    int t = threadIdx.x;
    int c = __ldg(&y[g_index[row]]);
    const float4* x4 = reinterpret_cast<const float4*>(x) + (size_t)row * 512;
    const float4* n4 = reinterpret_cast<const float4*>(g_cn) + (size_t)c * 512;
    float4* o4 = reinterpret_cast<float4*>(out) + (size_t)row * 512;

    float4 a0 = __ldcs(x4 + t);
    float4 a1 = __ldcs(x4 + t + 256);
    float4 b0 = __ldg(n4 + t);
    float4 b1 = __ldg(n4 + t + 256);
    float4 o0, o1;
    o0.x = 0.9f * a0.x + 0.1f * b0.x;
    o0.y = 0.9f * a0.y + 0.1f * b0.y;
    o0.z = 0.9f * a0.z + 0.1f * b0.z;
    o0.w = 0.9f * a0.w + 0.1f * b0.w;
    o1.x = 0.9f * a1.x + 0.1f * b1.x;
    o1.y = 0.9f * a1.y + 0.1f * b1.y;
    o1.z = 0.9f * a1.z + 0.1f * b1.z;
    o1.w = 0.9f * a1.w + 0.1f * b1.w;
    __stcs(o4 + t, o0);
    __stcs(o4 + t + 256, o1);

    if (t == 0) {
        long long p = (long long)B_ROWS * D_COLS + row;
        if (p < (long long)out_size) out[p] = (float)c;   // newY as numeric value
    }
}

// ---------------------------------------------------------------------------
// Permutation upload via kernel parameters (no memcpy nodes).
// ---------------------------------------------------------------------------
struct IdxChunk { unsigned short v[8192]; };

__global__ void upload_idx_kernel(IdxChunk ch, int off)
{
    int t = blockIdx.x * blockDim.x + threadIdx.x;
    if (t < 8192) g_index[off + t] = ch.v[t];
}

// ---------------------------------------------------------------------------
// Host: jax.random key derivation + permutation (2 stable-sort rounds).
// ---------------------------------------------------------------------------
extern "C" void kernel_launch(void* const* d_in, const int* in_sizes, int n_in,
                              void* d_out, int out_size)
{
    const float* x = (const float*)d_in[0];
    const int*   y = (const int*)d_in[1];
    float* out = (float*)d_out;

    uint32_t nk0, nk1, pk0, pk1;
    threefry2x32(0u, 42u, 0u, 0u, nk0, nk1);
    threefry2x32(0u, 42u, 0u, 1u, pk0, pk1);

    std::vector<uint16_t> perm(B_ROWS), tmp(B_ROWS);
    std::vector<uint64_t> buf(B_ROWS);
    for (int i = 0; i < B_ROWS; i++) perm[i] = (uint16_t)i;
    uint32_t k0 = pk0, k1 = pk1;
    const int NUM_ROUNDS = 2;   // ceil(3*log(16384)/log(2^32-1))
    for (int r = 0; r < NUM_ROUNDS; r++) {
        uint32_t t0, t1, s0, s1;
        threefry2x32(k0, k1, 0u, 0u, t0, t1);
        threefry2x32(k0, k1, 0u, 1u, s0, s1);
        k0 = t0; k1 = t1;
        for (int i = 0; i < B_ROWS; i++) {
            uint32_t b0, b1;
            threefry2x32(s0, s1, 0u, (uint32_t)i, b0, b1);
            buf[i] = ((uint64_t)(b0 ^ b1) << 32) | (uint32_t)i;
        }
        std::sort(buf.begin(), buf.end());
        for (int j = 0; j < B_ROWS; j++)
            tmp[j] = perm[(uint32_t)(buf[j] & 0xFFFFFFFFu)];
        perm.swap(tmp);
    }

    IdxChunk c0, c1;
    memcpy(c0.v, perm.data(),        8192 * sizeof(uint16_t));
    memcpy(c1.v, perm.data() + 8192, 8192 * sizeof(uint16_t));
    upload_idx_kernel<<<32, 256>>>(c0, 0);
    upload_idx_kernel<<<32, 256>>>(c1, 8192);

    build_csr_kernel<<<1, 1024>>>(y);
    dim3 sgrid(NCLS, 4);
    stats_noise_kernel<<<sgrid, 128>>>(x, nk0, nk1);
    out_kernel<<<B_ROWS, 256>>>(x, y, out, out_size);
}

// round 5
// speedup vs baseline: 1.2010x; 1.2010x over previous
#include <cuda_runtime.h>
#include <cstdint>
#include <cstring>
#include <vector>
#include <algorithm>

#define B_ROWS 16384
#define D_COLS 2048
#define NCLS   1000

// Scratch (device globals: allocation-free per harness rules)
__device__ unsigned short g_index[B_ROWS];          // permutation, host-computed
__device__ unsigned short g_rows[B_ROWS];           // row ids grouped by class (CSR)
__device__ int g_off[NCLS + 1];                     // CSR offsets
__device__ float g_cn[NCLS * D_COLS];               // class_noise matrix (8MB)

// ---------------------------------------------------------------------------
// JAX threefry2x32 (20 rounds), bit-exact. Host+device.
// ---------------------------------------------------------------------------
__host__ __device__ __forceinline__ void threefry2x32(
    uint32_t k0, uint32_t k1, uint32_t x0, uint32_t x1,
    uint32_t &o0, uint32_t &o1)
{
    uint32_t ks0 = k0, ks1 = k1, ks2 = k0 ^ k1 ^ 0x1BD11BDAu;
    x0 += ks0; x1 += ks1;
    const int R[2][4] = {{13, 15, 26, 6}, {17, 29, 16, 24}};
#pragma unroll
    for (int i = 0; i < 5; i++) {
#pragma unroll
        for (int j = 0; j < 4; j++) {
            int r = R[i & 1][j];
            x0 += x1;
            x1 = (x1 << r) | (x1 >> (32 - r));
            x1 ^= x0;
        }
        uint32_t a = (i + 1) % 3 == 0 ? ks0 : ((i + 1) % 3 == 1 ? ks1 : ks2);
        uint32_t b = (i + 2) % 3 == 0 ? ks0 : ((i + 2) % 3 == 1 ? ks1 : ks2);
        x0 += a;
        x1 += b + (uint32_t)(i + 1);
    }
    o0 = x0; o1 = x1;
}

// ---------------------------------------------------------------------------
// XLA f32 ErfInv (Giles polynomial)
// ---------------------------------------------------------------------------
__device__ __forceinline__ float erfinv_f32(float x)
{
    float w = -log1pf(-x * x);
    float p;
    if (w < 5.0f) {
        w -= 2.5f;
        p = 2.81022636e-08f;
        p = fmaf(p, w, 3.43273939e-07f);
        p = fmaf(p, w, -3.5233877e-06f);
        p = fmaf(p, w, -4.39150654e-06f);
        p = fmaf(p, w, 0.00021858087f);
        p = fmaf(p, w, -0.00125372503f);
        p = fmaf(p, w, -0.00417768164f);
        p = fmaf(p, w, 0.246640727f);
        p = fmaf(p, w, 1.50140941f);
    } else {
        w = sqrtf(w) - 3.0f;
        p = -0.000200214257f;
        p = fmaf(p, w, 0.000100950558f);
        p = fmaf(p, w, 0.00134934322f);
        p = fmaf(p, w, -0.00367342844f);
        p = fmaf(p, w, 0.00573950773f);
        p = fmaf(p, w, -0.0076224613f);
        p = fmaf(p, w, 0.00943887047f);
        p = fmaf(p, w, 1.00167406f);
        p = fmaf(p, w, 2.83297682f);
    }
    return p * x;
}

__device__ __forceinline__ float jax_normal(uint32_t nk0, uint32_t nk1, uint32_t idx)
{
    uint32_t b0, b1;
    threefry2x32(nk0, nk1, 0u, idx, b0, b1);
    uint32_t bits = b0 ^ b1;
    float f = __uint_as_float((bits >> 9) | 0x3f800000u);   // [1,2)
    const float lo = -0.99999994039535522461f;               // nextafter(-1,0)
    float u = fmaxf(lo, fmaf(f - 1.0f, 2.0f, lo));
    return 1.41421356237309504880f * erfinv_f32(u);
}

__device__ __forceinline__ float cn_val(float s, float q, float cnt,
                                        uint32_t nk0, uint32_t nk1, uint32_t flat)
{
    float mean = s / cnt;
    float var  = (q - cnt * mean * mean) / (cnt - 1.0f);
    float sd   = sqrtf(fmaxf(var, 0.0f));
    return mean + sd * jax_normal(nk0, nk1, flat);
}

// ---------------------------------------------------------------------------
// Kernel A: build per-class CSR of row indices, entirely in shared memory.
// Single CTA, 1024 threads. histogram -> scan -> smem scatter ->
// per-class insertion sort IN SMEM (LDS latency, 1000 threads parallel)
// -> coalesced write to g_rows. Deterministic ascending order per class.
// ---------------------------------------------------------------------------
__global__ __launch_bounds__(1024) void build_csr_kernel(const int* __restrict__ y)
{
    __shared__ int cnt[1024];
    __shared__ int sc[1024];
    __shared__ int cur[1024];
    __shared__ unsigned short rows_sm[B_ROWS];   // 32KB
    int t = threadIdx.x;
    cnt[t] = 0;
    __syncthreads();
    for (int i = t; i < B_ROWS; i += 1024) atomicAdd(&cnt[y[i]], 1);
    __syncthreads();
    sc[t] = cnt[t];
    __syncthreads();
    for (int d = 1; d < 1024; d <<= 1) {
        int add = (t >= d) ? sc[t - d] : 0;
        __syncthreads();
        sc[t] += add;
        __syncthreads();
    }
    int excl = (t == 0) ? 0 : sc[t - 1];   // exclusive prefix
    cur[t] = excl;
    if (t <= NCLS) g_off[t] = (t == 0) ? 0 : sc[t - 1];
    __syncthreads();
    for (int i = t; i < B_ROWS; i += 1024) {
        int c = y[i];
        int p = atomicAdd(&cur[c], 1);
        rows_sm[p] = (unsigned short)i;
    }
    __syncthreads();
    if (t < NCLS) {   // per-class insertion sort in smem (deterministic order)
        int s = excl, e = sc[t];
        for (int a = s + 1; a < e; a++) {
            unsigned short v = rows_sm[a];
            int b = a - 1;
            while (b >= s && rows_sm[b] > v) { rows_sm[b + 1] = rows_sm[b]; b--; }
            rows_sm[b + 1] = v;
        }
    }
    __syncthreads();
    // coalesced write-out (uint4 = 8 u16 per thread)
    uint4* dst = reinterpret_cast<uint4*>(g_rows);
    const uint4* src = reinterpret_cast<const uint4*>(rows_sm);
    for (int i = t; i < B_ROWS / 8; i += 1024) dst[i] = src[i];
}

// ---------------------------------------------------------------------------
// Kernel B: per-class stats fused with noise generation.
// grid (NCLS, 2): one CTA per (class, 1024-float D-half); 128 thr.
// Each thread: 2 col-chunks x 4-row unroll = 8 independent LDG.128 in flight.
// ---------------------------------------------------------------------------
__global__ __launch_bounds__(128) void stats_noise_kernel(
    const float* __restrict__ x, uint32_t nk0, uint32_t nk1)
{
    __shared__ unsigned short rows[256];
    int c = blockIdx.x;
    int t = threadIdx.x;
    int beg = __ldg(&g_off[c]);
    int n   = __ldg(&g_off[c + 1]) - beg;
    for (int i = t; i < n && i < 256; i += 128) rows[i] = g_rows[beg + i];
    __syncthreads();

    int col = blockIdx.y * 1024 + t * 4;               // first float4 (col), second at +512
    const float* xa = x + col;
    const float* xb = x + col + 512;
    float4 sA = {0,0,0,0}, qA = {0,0,0,0}, sB = {0,0,0,0}, qB = {0,0,0,0};

#define ACC(S, Q, V) \
    S.x += V.x; S.y += V.y; S.z += V.z; S.w += V.w; \
    Q.x += V.x*V.x; Q.y += V.y*V.y; Q.z += V.z*V.z; Q.w += V.w*V.w;

    int r = 0;
    for (; r + 4 <= n; r += 4) {
        size_t r0 = rows[r], r1 = rows[r + 1], r2 = rows[r + 2], r3 = rows[r + 3];
        float4 a0 = __ldcs(reinterpret_cast<const float4*>(xa + r0 * D_COLS));
        float4 b0 = __ldcs(reinterpret_cast<const float4*>(xb + r0 * D_COLS));
        float4 a1 = __ldcs(reinterpret_cast<const float4*>(xa + r1 * D_COLS));
        float4 b1 = __ldcs(reinterpret_cast<const float4*>(xb + r1 * D_COLS));
        float4 a2 = __ldcs(reinterpret_cast<const float4*>(xa + r2 * D_COLS));
        float4 b2 = __ldcs(reinterpret_cast<const float4*>(xb + r2 * D_COLS));
        float4 a3 = __ldcs(reinterpret_cast<const float4*>(xa + r3 * D_COLS));
        float4 b3 = __ldcs(reinterpret_cast<const float4*>(xb + r3 * D_COLS));
        ACC(sA, qA, a0) ACC(sB, qB, b0)
        ACC(sA, qA, a1) ACC(sB, qB, b1)
        ACC(sA, qA, a2) ACC(sB, qB, b2)
        ACC(sA, qA, a3) ACC(sB, qB, b3)
    }
    for (; r < n; r++) {
        size_t rr = (r < 256) ? (size_t)rows[r] : (size_t)g_rows[beg + r];
        float4 a = __ldcs(reinterpret_cast<const float4*>(xa + rr * D_COLS));
        float4 b = __ldcs(reinterpret_cast<const float4*>(xb + rr * D_COLS));
        ACC(sA, qA, a) ACC(sB, qB, b)
    }
#undef ACC

    float cnt = (float)n;
    uint32_t flat = (uint32_t)c * (uint32_t)D_COLS + (uint32_t)col;
    float4 oA, oB;
    oA.x = cn_val(sA.x, qA.x, cnt, nk0, nk1, flat + 0u);
    oA.y = cn_val(sA.y, qA.y, cnt, nk0, nk1, flat + 1u);
    oA.z = cn_val(sA.z, qA.z, cnt, nk0, nk1, flat + 2u);
    oA.w = cn_val(sA.w, qA.w, cnt, nk0, nk1, flat + 3u);
    oB.x = cn_val(sB.x, qB.x, cnt, nk0, nk1, flat + 512u);
    oB.y = cn_val(sB.y, qB.y, cnt, nk0, nk1, flat + 513u);
    oB.z = cn_val(sB.z, qB.z, cnt, nk0, nk1, flat + 514u);
    oB.w = cn_val(sB.w, qB.w, cnt, nk0, nk1, flat + 515u);
    *reinterpret_cast<float4*>(g_cn + (size_t)c * D_COLS + col)       = oA;
    *reinterpret_cast<float4*>(g_cn + (size_t)c * D_COLS + col + 512) = oB;
}

// ---------------------------------------------------------------------------
// Kernel C: out = 0.9*x + 0.1*cn[newY[row]], newY[row] = y[perm[row]]
// ---------------------------------------------------------------------------
__global__ __launch_bounds__(256) void out_kernel(
    const float* __restrict__ x, const int* __restrict__ y,
    float* __restrict__ out, int out_size)
{
    int row = blockIdx.x;
    int t = threadIdx.x;
    int c = __ldg(&y[g_index[row]]);
    const float4* x4 = reinterpret_cast<const float4*>(x) + (size_t)row * 512;
    const float4* n4 = reinterpret_cast<const float4*>(g_cn) + (size_t)c * 512;
    float4* o4 = reinterpret_cast<float4*>(out) + (size_t)row * 512;

    float4 a0 = __ldcs(x4 + t);
    float4 a1 = __ldcs(x4 + t + 256);
    float4 b0 = __ldg(n4 + t);
    float4 b1 = __ldg(n4 + t + 256);
    float4 o0, o1;
    o0.x = 0.9f * a0.x + 0.1f * b0.x;
    o0.y = 0.9f * a0.y + 0.1f * b0.y;
    o0.z = 0.9f * a0.z + 0.1f * b0.z;
    o0.w = 0.9f * a0.w + 0.1f * b0.w;
    o1.x = 0.9f * a1.x + 0.1f * b1.x;
    o1.y = 0.9f * a1.y + 0.1f * b1.y;
    o1.z = 0.9f * a1.z + 0.1f * b1.z;
    o1.w = 0.9f * a1.w + 0.1f * b1.w;
    __stcs(o4 + t, o0);
    __stcs(o4 + t + 256, o1);

    if (t == 0) {
        long long p = (long long)B_ROWS * D_COLS + row;
        if (p < (long long)out_size) out[p] = (float)c;   // newY as numeric value
    }
}

// ---------------------------------------------------------------------------
// Permutation upload via kernel parameters (no memcpy nodes).
// ---------------------------------------------------------------------------
struct IdxChunk { unsigned short v[8192]; };

__global__ void upload_idx_kernel(IdxChunk ch, int off)
{
    int t = blockIdx.x * blockDim.x + threadIdx.x;
    if (t < 8192) g_index[off + t] = ch.v[t];
}

// ---------------------------------------------------------------------------
// Host: jax.random key derivation + permutation (2 stable-sort rounds).
// ---------------------------------------------------------------------------
extern "C" void kernel_launch(void* const* d_in, const int* in_sizes, int n_in,
                              void* d_out, int out_size)
{
    const float* x = (const float*)d_in[0];
    const int*   y = (const int*)d_in[1];
    float* out = (float*)d_out;

    uint32_t nk0, nk1, pk0, pk1;
    threefry2x32(0u, 42u, 0u, 0u, nk0, nk1);
    threefry2x32(0u, 42u, 0u, 1u, pk0, pk1);

    std::vector<uint16_t> perm(B_ROWS), tmp(B_ROWS);
    std::vector<uint64_t> buf(B_ROWS);
    for (int i = 0; i < B_ROWS; i++) perm[i] = (uint16_t)i;
    uint32_t k0 = pk0, k1 = pk1;
    const int NUM_ROUNDS = 2;   // ceil(3*log(16384)/log(2^32-1))
    for (int r = 0; r < NUM_ROUNDS; r++) {
        uint32_t t0, t1, s0, s1;
        threefry2x32(k0, k1, 0u, 0u, t0, t1);
        threefry2x32(k0, k1, 0u, 1u, s0, s1);
        k0 = t0; k1 = t1;
        for (int i = 0; i < B_ROWS; i++) {
            uint32_t b0, b1;
            threefry2x32(s0, s1, 0u, (uint32_t)i, b0, b1);
            buf[i] = ((uint64_t)(b0 ^ b1) << 32) | (uint32_t)i;
        }
        std::sort(buf.begin(), buf.end());
        for (int j = 0; j < B_ROWS; j++)
            tmp[j] = perm[(uint32_t)(buf[j] & 0xFFFFFFFFu)];
        perm.swap(tmp);
    }

    IdxChunk c0, c1;
    memcpy(c0.v, perm.data(),        8192 * sizeof(uint16_t));
    memcpy(c1.v, perm.data() + 8192, 8192 * sizeof(uint16_t));
    upload_idx_kernel<<<32, 256>>>(c0, 0);
    upload_idx_kernel<<<32, 256>>>(c1, 8192);

    build_csr_kernel<<<1, 1024>>>(y);
    dim3 sgrid(NCLS, 2);
    stats_noise_kernel<<<sgrid, 128>>>(x, nk0, nk1);
    out_kernel<<<B_ROWS, 256>>>(x, y, out, out_size);
}

// round 6
// speedup vs baseline: 1.3158x; 1.0956x over previous
#include <cuda_runtime.h>
#include <cstdint>
#include <cstring>
#include <vector>
#include <algorithm>

#define B_ROWS 16384
#define D_COLS 2048
#define NCLS   1000

// Scratch (device globals: allocation-free per harness rules)
__device__ unsigned short g_index[B_ROWS];          // permutation, host-computed
__device__ unsigned short g_rows[B_ROWS];           // row ids grouped by class (CSR, unsorted)
__device__ int g_off[NCLS + 1];                     // CSR offsets
__device__ float g_cn[NCLS * D_COLS];               // class_noise matrix (8MB)

// ---------------------------------------------------------------------------
// JAX threefry2x32 (20 rounds), bit-exact. Host+device.
// ---------------------------------------------------------------------------
__host__ __device__ __forceinline__ void threefry2x32(
    uint32_t k0, uint32_t k1, uint32_t x0, uint32_t x1,
    uint32_t &o0, uint32_t &o1)
{
    uint32_t ks0 = k0, ks1 = k1, ks2 = k0 ^ k1 ^ 0x1BD11BDAu;
    x0 += ks0; x1 += ks1;
    const int R[2][4] = {{13, 15, 26, 6}, {17, 29, 16, 24}};
#pragma unroll
    for (int i = 0; i < 5; i++) {
#pragma unroll
        for (int j = 0; j < 4; j++) {
            int r = R[i & 1][j];
            x0 += x1;
            x1 = (x1 << r) | (x1 >> (32 - r));
            x1 ^= x0;
        }
        uint32_t a = (i + 1) % 3 == 0 ? ks0 : ((i + 1) % 3 == 1 ? ks1 : ks2);
        uint32_t b = (i + 2) % 3 == 0 ? ks0 : ((i + 2) % 3 == 1 ? ks1 : ks2);
        x0 += a;
        x1 += b + (uint32_t)(i + 1);
    }
    o0 = x0; o1 = x1;
}

// ---------------------------------------------------------------------------
// XLA f32 ErfInv (Giles polynomial)
// ---------------------------------------------------------------------------
__device__ __forceinline__ float erfinv_f32(float x)
{
    float w = -log1pf(-x * x);
    float p;
    if (w < 5.0f) {
        w -= 2.5f;
        p = 2.81022636e-08f;
        p = fmaf(p, w, 3.43273939e-07f);
        p = fmaf(p, w, -3.5233877e-06f);
        p = fmaf(p, w, -4.39150654e-06f);
        p = fmaf(p, w, 0.00021858087f);
        p = fmaf(p, w, -0.00125372503f);
        p = fmaf(p, w, -0.00417768164f);
        p = fmaf(p, w, 0.246640727f);
        p = fmaf(p, w, 1.50140941f);
    } else {
        w = sqrtf(w) - 3.0f;
        p = -0.000200214257f;
        p = fmaf(p, w, 0.000100950558f);
        p = fmaf(p, w, 0.00134934322f);
        p = fmaf(p, w, -0.00367342844f);
        p = fmaf(p, w, 0.00573950773f);
        p = fmaf(p, w, -0.0076224613f);
        p = fmaf(p, w, 0.00943887047f);
        p = fmaf(p, w, 1.00167406f);
        p = fmaf(p, w, 2.83297682f);
    }
    return p * x;
}

__device__ __forceinline__ float jax_normal(uint32_t nk0, uint32_t nk1, uint32_t idx)
{
    uint32_t b0, b1;
    threefry2x32(nk0, nk1, 0u, idx, b0, b1);
    uint32_t bits = b0 ^ b1;
    float f = __uint_as_float((bits >> 9) | 0x3f800000u);   // [1,2)
    const float lo = -0.99999994039535522461f;               // nextafter(-1,0)
    float u = fmaxf(lo, fmaf(f - 1.0f, 2.0f, lo));
    return 1.41421356237309504880f * erfinv_f32(u);
}

__device__ __forceinline__ float cn_val(float s, float q, float cnt,
                                        uint32_t nk0, uint32_t nk1, uint32_t flat)
{
    float mean = s / cnt;
    float var  = (q - cnt * mean * mean) / (cnt - 1.0f);
    float sd   = sqrtf(fmaxf(var, 0.0f));
    return mean + sd * jax_normal(nk0, nk1, flat);
}

// ---------------------------------------------------------------------------
// Kernel A: build per-class CSR of row indices (NO sort here — sorting is
// done cheaply in parallel by each stats CTA). Single CTA, 1024 threads.
// histogram -> Hillis-Steele scan -> smem scatter -> coalesced write-out.
// ---------------------------------------------------------------------------
__global__ __launch_bounds__(1024) void build_csr_kernel(const int* __restrict__ y)
{
    __shared__ int cnt[1024];
    __shared__ int sc[1024];
    __shared__ int cur[1024];
    __shared__ unsigned short rows_sm[B_ROWS];   // 32KB
    int t = threadIdx.x;
    cnt[t] = 0;
    __syncthreads();
    for (int i = t; i < B_ROWS; i += 1024) atomicAdd(&cnt[y[i]], 1);
    __syncthreads();
    sc[t] = cnt[t];
    __syncthreads();
    for (int d = 1; d < 1024; d <<= 1) {
        int add = (t >= d) ? sc[t - d] : 0;
        __syncthreads();
        sc[t] += add;
        __syncthreads();
    }
    int excl = (t == 0) ? 0 : sc[t - 1];   // exclusive prefix
    cur[t] = excl;
    if (t <= NCLS) g_off[t] = (t == 0) ? 0 : sc[t - 1];
    __syncthreads();
    for (int i = t; i < B_ROWS; i += 1024) {
        int c = y[i];
        int p = atomicAdd(&cur[c], 1);
        rows_sm[p] = (unsigned short)i;
    }
    __syncthreads();
    uint4* dst = reinterpret_cast<uint4*>(g_rows);
    const uint4* src = reinterpret_cast<const uint4*>(rows_sm);
    for (int i = t; i < B_ROWS / 8; i += 1024) dst[i] = src[i];
}

// ---------------------------------------------------------------------------
// Kernel B: per-class stats fused with noise generation (R4-proven shape).
// grid (NCLS, 4): one CTA per (class, 512-float D-chunk); 128 thr x 1 float4.
// Row list sorted in-CTA via odd-even transposition (deterministic order);
// precomputed element offsets cut per-load IMAD work.
// Default-cached x loads leave x L2-resident for out_kernel.
// ---------------------------------------------------------------------------
__global__ __launch_bounds__(128) void stats_noise_kernel(
    const float* __restrict__ x, uint32_t nk0, uint32_t nk1)
{
    __shared__ unsigned short rows[256];
    __shared__ unsigned int offs[256];
    int c = blockIdx.x;
    int t = threadIdx.x;
    int beg = __ldg(&g_off[c]);
    int n   = __ldg(&g_off[c + 1]) - beg;
    int nc  = min(n, 256);
    for (int i = t; i < nc; i += 128) rows[i] = g_rows[beg + i];
    __syncthreads();
    // odd-even transposition sort, nc phases (deterministic ascending order)
    for (int ph = 0; ph < nc; ph++) {
        int i = 2 * t + (ph & 1);
        if (i + 1 < nc) {
            unsigned short a = rows[i], b = rows[i + 1];
            if (a > b) { rows[i] = b; rows[i + 1] = a; }
        }
        __syncthreads();
    }
    for (int i = t; i < nc; i += 128) offs[i] = (unsigned int)rows[i] * D_COLS;
    __syncthreads();

    int col = blockIdx.y * 512 + t * 4;                 // float index in row
    const float* xb = x + col;
    float4 s = {0, 0, 0, 0}, q = {0, 0, 0, 0};

#define ACC(V) \
    s.x += V.x; s.y += V.y; s.z += V.z; s.w += V.w; \
    q.x += V.x*V.x; q.y += V.y*V.y; q.z += V.z*V.z; q.w += V.w*V.w;

    int r = 0;
    for (; r + 4 <= n; r += 4) {
        unsigned int o0 = offs[r], o1 = offs[r + 1], o2 = offs[r + 2], o3 = offs[r + 3];
        float4 v0 = *reinterpret_cast<const float4*>(xb + o0);
        float4 v1 = *reinterpret_cast<const float4*>(xb + o1);
        float4 v2 = *reinterpret_cast<const float4*>(xb + o2);
        float4 v3 = *reinterpret_cast<const float4*>(xb + o3);
        ACC(v0) ACC(v1) ACC(v2) ACC(v3)
    }
    for (; r < n; r++) {
        unsigned int oo = (r < 256) ? offs[r] : (unsigned int)g_rows[beg + r] * D_COLS;
        float4 v = *reinterpret_cast<const float4*>(xb + oo);
        ACC(v)
    }
#undef ACC

    float cnt = (float)n;
    uint32_t flat = (uint32_t)c * (uint32_t)D_COLS + (uint32_t)col;
    float4 o;
    o.x = cn_val(s.x, q.x, cnt, nk0, nk1, flat + 0u);
    o.y = cn_val(s.y, q.y, cnt, nk0, nk1, flat + 1u);
    o.z = cn_val(s.z, q.z, cnt, nk0, nk1, flat + 2u);
    o.w = cn_val(s.w, q.w, cnt, nk0, nk1, flat + 3u);
    *reinterpret_cast<float4*>(g_cn + (size_t)c * D_COLS + col) = o;
}

// ---------------------------------------------------------------------------
// Kernel C: out = 0.9*x + 0.1*cn[newY[row]], newY[row] = y[perm[row]]
// x loads __ldcs: hit L2 leftovers from stats, evict after use.
// ---------------------------------------------------------------------------
__global__ __launch_bounds__(256) void out_kernel(
    const float* __restrict__ x, const int* __restrict__ y,
    float* __restrict__ out, int out_size)
{
    int row = blockIdx.x;
    int t = threadIdx.x;
    int c = __ldg(&y[g_index[row]]);
    const float4* x4 = reinterpret_cast<const float4*>(x) + (size_t)row * 512;
    const float4* n4 = reinterpret_cast<const float4*>(g_cn) + (size_t)c * 512;
    float4* o4 = reinterpret_cast<float4*>(out) + (size_t)row * 512;

    float4 a0 = __ldcs(x4 + t);
    float4 a1 = __ldcs(x4 + t + 256);
    float4 b0 = __ldg(n4 + t);
    float4 b1 = __ldg(n4 + t + 256);
    float4 o0, o1;
    o0.x = 0.9f * a0.x + 0.1f * b0.x;
    o0.y = 0.9f * a0.y + 0.1f * b0.y;
    o0.z = 0.9f * a0.z + 0.1f * b0.z;
    o0.w = 0.9f * a0.w + 0.1f * b0.w;
    o1.x = 0.9f * a1.x + 0.1f * b1.x;
    o1.y = 0.9f * a1.y + 0.1f * b1.y;
    o1.z = 0.9f * a1.z + 0.1f * b1.z;
    o1.w = 0.9f * a1.w + 0.1f * b1.w;
    __stcs(o4 + t, o0);
    __stcs(o4 + t + 256, o1);

    if (t == 0) {
        long long p = (long long)B_ROWS * D_COLS + row;
        if (p < (long long)out_size) out[p] = (float)c;   // newY as numeric value
    }
}

// ---------------------------------------------------------------------------
// Permutation upload via kernel parameters (no memcpy nodes).
// ---------------------------------------------------------------------------
struct IdxChunk { unsigned short v[8192]; };

__global__ void upload_idx_kernel(IdxChunk ch, int off)
{
    int t = blockIdx.x * blockDim.x + threadIdx.x;
    if (t < 8192) g_index[off + t] = ch.v[t];
}

// ---------------------------------------------------------------------------
// Host: jax.random key derivation + permutation (2 stable-sort rounds).
// ---------------------------------------------------------------------------
extern "C" void kernel_launch(void* const* d_in, const int* in_sizes, int n_in,
                              void* d_out, int out_size)
{
    const float* x = (const float*)d_in[0];
    const int*   y = (const int*)d_in[1];
    float* out = (float*)d_out;

    uint32_t nk0, nk1, pk0, pk1;
    threefry2x32(0u, 42u, 0u, 0u, nk0, nk1);
    threefry2x32(0u, 42u, 0u, 1u, pk0, pk1);

    std::vector<uint16_t> perm(B_ROWS), tmp(B_ROWS);
    std::vector<uint64_t> buf(B_ROWS);
    for (int i = 0; i < B_ROWS; i++) perm[i] = (uint16_t)i;
    uint32_t k0 = pk0, k1 = pk1;
    const int NUM_ROUNDS = 2;   // ceil(3*log(16384)/log(2^32-1))
    for (int r = 0; r < NUM_ROUNDS; r++) {
        uint32_t t0, t1, s0, s1;
        threefry2x32(k0, k1, 0u, 0u, t0, t1);
        threefry2x32(k0, k1, 0u, 1u, s0, s1);
        k0 = t0; k1 = t1;
        for (int i = 0; i < B_ROWS; i++) {
            uint32_t b0, b1;
            threefry2x32(s0, s1, 0u, (uint32_t)i, b0, b1);
            buf[i] = ((uint64_t)(b0 ^ b1) << 32) | (uint32_t)i;
        }
        std::sort(buf.begin(), buf.end());
        for (int j = 0; j < B_ROWS; j++)
            tmp[j] = perm[(uint32_t)(buf[j] & 0xFFFFFFFFu)];
        perm.swap(tmp);
    }

    IdxChunk c0, c1;
    memcpy(c0.v, perm.data(),        8192 * sizeof(uint16_t));
    memcpy(c1.v, perm.data() + 8192, 8192 * sizeof(uint16_t));
    upload_idx_kernel<<<32, 256>>>(c0, 0);
    upload_idx_kernel<<<32, 256>>>(c1, 8192);

    build_csr_kernel<<<1, 1024>>>(y);
    dim3 sgrid(NCLS, 4);
    stats_noise_kernel<<<sgrid, 128>>>(x, nk0, nk1);
    out_kernel<<<B_ROWS, 256>>>(x, y, out, out_size);
}

// round 7
// speedup vs baseline: 1.3208x; 1.0037x over previous
#include <cuda_runtime.h>
#include <cstdint>
#include <cstring>
#include <vector>
#include <algorithm>

#define B_ROWS 16384
#define D_COLS 2048
#define NCLS   1000

// Scratch (device globals: allocation-free per harness rules)
__device__ unsigned short g_index[B_ROWS];          // permutation, host-computed
__device__ unsigned short g_rows[B_ROWS];           // row ids grouped by class (CSR, unsorted)
__device__ int g_off[NCLS + 1];                     // CSR offsets
__device__ float g_cn[NCLS * D_COLS];               // class_noise matrix (8MB)

// packed f32x2 helpers (sm_103a; ptxas never emits these from C++)
__device__ __forceinline__ void addx2(unsigned long long &acc, unsigned long long v) {
    asm("add.rn.f32x2 %0, %1, %2;" : "=l"(acc) : "l"(acc), "l"(v));
}
__device__ __forceinline__ void fmax2(unsigned long long &acc, unsigned long long a,
                                      unsigned long long b) {
    asm("fma.rn.f32x2 %0, %1, %2, %3;" : "=l"(acc) : "l"(a), "l"(b), "l"(acc));
}
__device__ __forceinline__ void unpackx2(unsigned long long v, float &lo, float &hi) {
    unsigned int l, h;
    asm("mov.b64 {%0, %1}, %2;" : "=r"(l), "=r"(h) : "l"(v));
    lo = __uint_as_float(l); hi = __uint_as_float(h);
}

// ---------------------------------------------------------------------------
// JAX threefry2x32 (20 rounds), bit-exact. Host+device.
// ---------------------------------------------------------------------------
__host__ __device__ __forceinline__ void threefry2x32(
    uint32_t k0, uint32_t k1, uint32_t x0, uint32_t x1,
    uint32_t &o0, uint32_t &o1)
{
    uint32_t ks0 = k0, ks1 = k1, ks2 = k0 ^ k1 ^ 0x1BD11BDAu;
    x0 += ks0; x1 += ks1;
    const int R[2][4] = {{13, 15, 26, 6}, {17, 29, 16, 24}};
#pragma unroll
    for (int i = 0; i < 5; i++) {
#pragma unroll
        for (int j = 0; j < 4; j++) {
            int r = R[i & 1][j];
            x0 += x1;
            x1 = (x1 << r) | (x1 >> (32 - r));
            x1 ^= x0;
        }
        uint32_t a = (i + 1) % 3 == 0 ? ks0 : ((i + 1) % 3 == 1 ? ks1 : ks2);
        uint32_t b = (i + 2) % 3 == 0 ? ks0 : ((i + 2) % 3 == 1 ? ks1 : ks2);
        x0 += a;
        x1 += b + (uint32_t)(i + 1);
    }
    o0 = x0; o1 = x1;
}

// ---------------------------------------------------------------------------
// XLA f32 ErfInv (Giles polynomial)
// ---------------------------------------------------------------------------
__device__ __forceinline__ float erfinv_f32(float x)
{
    float w = -log1pf(-x * x);
    float p;
    if (w < 5.0f) {
        w -= 2.5f;
        p = 2.81022636e-08f;
        p = fmaf(p, w, 3.43273939e-07f);
        p = fmaf(p, w, -3.5233877e-06f);
        p = fmaf(p, w, -4.39150654e-06f);
        p = fmaf(p, w, 0.00021858087f);
        p = fmaf(p, w, -0.00125372503f);
        p = fmaf(p, w, -0.00417768164f);
        p = fmaf(p, w, 0.246640727f);
        p = fmaf(p, w, 1.50140941f);
    } else {
        w = sqrtf(w) - 3.0f;
        p = -0.000200214257f;
        p = fmaf(p, w, 0.000100950558f);
        p = fmaf(p, w, 0.00134934322f);
        p = fmaf(p, w, -0.00367342844f);
        p = fmaf(p, w, 0.00573950773f);
        p = fmaf(p, w, -0.0076224613f);
        p = fmaf(p, w, 0.00943887047f);
        p = fmaf(p, w, 1.00167406f);
        p = fmaf(p, w, 2.83297682f);
    }
    return p * x;
}

__device__ __forceinline__ float jax_normal(uint32_t nk0, uint32_t nk1, uint32_t idx)
{
    uint32_t b0, b1;
    threefry2x32(nk0, nk1, 0u, idx, b0, b1);
    uint32_t bits = b0 ^ b1;
    float f = __uint_as_float((bits >> 9) | 0x3f800000u);   // [1,2)
    const float lo = -0.99999994039535522461f;               // nextafter(-1,0)
    float u = fmaxf(lo, fmaf(f - 1.0f, 2.0f, lo));
    return 1.41421356237309504880f * erfinv_f32(u);
}

__device__ __forceinline__ float cn_val(float s, float q, float cnt,
                                        uint32_t nk0, uint32_t nk1, uint32_t flat)
{
    float mean = s / cnt;
    float var  = (q - cnt * mean * mean) / (cnt - 1.0f);
    float sd   = sqrtf(fmaxf(var, 0.0f));
    return mean + sd * jax_normal(nk0, nk1, flat);
}

// ---------------------------------------------------------------------------
// Kernel A: build per-class CSR of row indices (sorting done per stats CTA).
// Single CTA, 1024 threads: histogram -> scan -> smem scatter -> write-out.
// ---------------------------------------------------------------------------
__global__ __launch_bounds__(1024) void build_csr_kernel(const int* __restrict__ y)
{
    __shared__ int cnt[1024];
    __shared__ int sc[1024];
    __shared__ int cur[1024];
    __shared__ unsigned short rows_sm[B_ROWS];   // 32KB
    int t = threadIdx.x;
    cnt[t] = 0;
    __syncthreads();
    for (int i = t; i < B_ROWS; i += 1024) atomicAdd(&cnt[y[i]], 1);
    __syncthreads();
    sc[t] = cnt[t];
    __syncthreads();
    for (int d = 1; d < 1024; d <<= 1) {
        int add = (t >= d) ? sc[t - d] : 0;
        __syncthreads();
        sc[t] += add;
        __syncthreads();
    }
    int excl = (t == 0) ? 0 : sc[t - 1];   // exclusive prefix
    cur[t] = excl;
    if (t <= NCLS) g_off[t] = (t == 0) ? 0 : sc[t - 1];
    __syncthreads();
    for (int i = t; i < B_ROWS; i += 1024) {
        int c = y[i];
        int p = atomicAdd(&cur[c], 1);
        rows_sm[p] = (unsigned short)i;
    }
    __syncthreads();
    uint4* dst = reinterpret_cast<uint4*>(g_rows);
    const uint4* src = reinterpret_cast<const uint4*>(rows_sm);
    for (int i = t; i < B_ROWS / 8; i += 1024) dst[i] = src[i];
}

// ---------------------------------------------------------------------------
// Kernel B: per-class stats fused with noise generation.
// grid (NCLS, 4): one CTA per (class, 512-float D-chunk); 128 thr x 1 float4.
// In-CTA odd-even sort of row list (deterministic ascending order).
// Accumulation with packed f32x2 add/fma (bit-identical per lane, half the
// FMA-pipe instructions -> less issue pressure feeding the LSU).
// ---------------------------------------------------------------------------
__global__ __launch_bounds__(128) void stats_noise_kernel(
    const float* __restrict__ x, uint32_t nk0, uint32_t nk1)
{
    __shared__ unsigned short rows[256];
    __shared__ unsigned int offs[256];
    int c = blockIdx.x;
    int t = threadIdx.x;
    int beg = __ldg(&g_off[c]);
    int n   = __ldg(&g_off[c + 1]) - beg;
    int nc  = min(n, 256);
    for (int i = t; i < nc; i += 128) rows[i] = g_rows[beg + i];
    __syncthreads();
    for (int ph = 0; ph < nc; ph++) {          // odd-even transposition sort
        int i = 2 * t + (ph & 1);
        if (i + 1 < nc) {
            unsigned short a = rows[i], b = rows[i + 1];
            if (a > b) { rows[i] = b; rows[i + 1] = a; }
        }
        __syncthreads();
    }
    for (int i = t; i < nc; i += 128) offs[i] = (unsigned int)rows[i] * D_COLS;
    __syncthreads();

    int col = blockIdx.y * 512 + t * 4;                 // float index in row
    const float* xb = x + col;
    unsigned long long s01 = 0, s23 = 0, q01 = 0, q23 = 0;  // packed f32x2 accum

#define ACC(V) { \
    addx2(s01, V.x); addx2(s23, V.y); \
    fmax2(q01, V.x, V.x); fmax2(q23, V.y, V.y); }

    int r = 0;
    for (; r + 4 <= n; r += 4) {
        unsigned int o0 = offs[r], o1 = offs[r + 1], o2 = offs[r + 2], o3 = offs[r + 3];
        ulonglong2 v0 = *reinterpret_cast<const ulonglong2*>(xb + o0);
        ulonglong2 v1 = *reinterpret_cast<const ulonglong2*>(xb + o1);
        ulonglong2 v2 = *reinterpret_cast<const ulonglong2*>(xb + o2);
        ulonglong2 v3 = *reinterpret_cast<const ulonglong2*>(xb + o3);
        ACC(v0) ACC(v1) ACC(v2) ACC(v3)
    }
    for (; r < n; r++) {
        unsigned int oo = (r < 256) ? offs[r] : (unsigned int)g_rows[beg + r] * D_COLS;
        ulonglong2 v = *reinterpret_cast<const ulonglong2*>(xb + oo);
        ACC(v)
    }
#undef ACC

    float4 s, q;
    unpackx2(s01, s.x, s.y); unpackx2(s23, s.z, s.w);
    unpackx2(q01, q.x, q.y); unpackx2(q23, q.z, q.w);

    float cnt = (float)n;
    uint32_t flat = (uint32_t)c * (uint32_t)D_COLS + (uint32_t)col;
    float4 o;
    o.x = cn_val(s.x, q.x, cnt, nk0, nk1, flat + 0u);
    o.y = cn_val(s.y, q.y, cnt, nk0, nk1, flat + 1u);
    o.z = cn_val(s.z, q.z, cnt, nk0, nk1, flat + 2u);
    o.w = cn_val(s.w, q.w, cnt, nk0, nk1, flat + 3u);
    *reinterpret_cast<float4*>(g_cn + (size_t)c * D_COLS + col) = o;
}

// ---------------------------------------------------------------------------
// Kernel C: out = 0.9*x + 0.1*cn[newY[row]] via packed f32x2.
// ---------------------------------------------------------------------------
__global__ __launch_bounds__(256) void out_kernel(
    const float* __restrict__ x, const int* __restrict__ y,
    float* __restrict__ out, int out_size)
{
    int row = blockIdx.x;
    int t = threadIdx.x;
    int c = __ldg(&y[g_index[row]]);
    const float4* x4 = reinterpret_cast<const float4*>(x) + (size_t)row * 512;
    const float4* n4 = reinterpret_cast<const float4*>(g_cn) + (size_t)c * 512;
    float4* o4 = reinterpret_cast<float4*>(out) + (size_t)row * 512;

    float4 a0 = __ldcs(x4 + t);
    float4 a1 = __ldcs(x4 + t + 256);
    float4 b0 = __ldg(n4 + t);
    float4 b1 = __ldg(n4 + t + 256);

    const unsigned long long C09 = 0x3f6666663f666666ull;  // {0.9f, 0.9f}
    const unsigned long long C01 = 0x3dcccccd3dcccccdull;  // {0.1f, 0.1f}
#define BLEND(A, O) { \
    ulonglong2 av = *reinterpret_cast<ulonglong2*>(&A); \
    ulonglong2 bv = *reinterpret_cast<ulonglong2*>(&O); \
    unsigned long long r0, r1; \
    asm("mul.rn.f32x2 %0, %1, %2;" : "=l"(r0) : "l"(av.x), "l"(C09)); \
    asm("mul.rn.f32x2 %0, %1, %2;" : "=l"(r1) : "l"(av.y), "l"(C09)); \
    asm("fma.rn.f32x2 %0, %1, %2, %3;" : "=l"(r0) : "l"(bv.x), "l"(C01), "l"(r0)); \
    asm("fma.rn.f32x2 %0, %1, %2, %3;" : "=l"(r1) : "l"(bv.y), "l"(C01), "l"(r1)); \
    av.x = r0; av.y = r1; \
    A = *reinterpret_cast<float4*>(&av); }

    BLEND(a0, b0)
    BLEND(a1, b1)
#undef BLEND
    __stcs(o4 + t, a0);
    __stcs(o4 + t + 256, a1);

    if (t == 0) {
        long long p = (long long)B_ROWS * D_COLS + row;
        if (p < (long long)out_size) out[p] = (float)c;   // newY as numeric value
    }
}

// ---------------------------------------------------------------------------
// Permutation upload via kernel parameters (no memcpy nodes).
// ---------------------------------------------------------------------------
struct IdxChunk { unsigned short v[8192]; };

__global__ void upload_idx_kernel(IdxChunk ch, int off)
{
    int t = blockIdx.x * blockDim.x + threadIdx.x;
    if (t < 8192) g_index[off + t] = ch.v[t];
}

// ---------------------------------------------------------------------------
// Host: jax.random key derivation + permutation (2 stable-sort rounds).
// ---------------------------------------------------------------------------
extern "C" void kernel_launch(void* const* d_in, const int* in_sizes, int n_in,
                              void* d_out, int out_size)
{
    const float* x = (const float*)d_in[0];
    const int*   y = (const int*)d_in[1];
    float* out = (float*)d_out;

    uint32_t nk0, nk1, pk0, pk1;
    threefry2x32(0u, 42u, 0u, 0u, nk0, nk1);
    threefry2x32(0u, 42u, 0u, 1u, pk0, pk1);

    std::vector<uint16_t> perm(B_ROWS), tmp(B_ROWS);
    std::vector<uint64_t> buf(B_ROWS);
    for (int i = 0; i < B_ROWS; i++) perm[i] = (uint16_t)i;
    uint32_t k0 = pk0, k1 = pk1;
    const int NUM_ROUNDS = 2;   // ceil(3*log(16384)/log(2^32-1))
    for (int r = 0; r < NUM_ROUNDS; r++) {
        uint32_t t0, t1, s0, s1;
        threefry2x32(k0, k1, 0u, 0u, t0, t1);
        threefry2x32(k0, k1, 0u, 1u, s0, s1);
        k0 = t0; k1 = t1;
        for (int i = 0; i < B_ROWS; i++) {
            uint32_t b0, b1;
            threefry2x32(s0, s1, 0u, (uint32_t)i, b0, b1);
            buf[i] = ((uint64_t)(b0 ^ b1) << 32) | (uint32_t)i;
        }
        std::sort(buf.begin(), buf.end());
        for (int j = 0; j < B_ROWS; j++)
            tmp[j] = perm[(uint32_t)(buf[j] & 0xFFFFFFFFu)];
        perm.swap(tmp);
    }

    IdxChunk c0, c1;
    memcpy(c0.v, perm.data(),        8192 * sizeof(uint16_t));
    memcpy(c1.v, perm.data() + 8192, 8192 * sizeof(uint16_t));
    upload_idx_kernel<<<32, 256>>>(c0, 0);
    upload_idx_kernel<<<32, 256>>>(c1, 8192);

    build_csr_kernel<<<1, 1024>>>(y);
    dim3 sgrid(NCLS, 4);
    stats_noise_kernel<<<sgrid, 128>>>(x, nk0, nk1);
    out_kernel<<<B_ROWS, 256>>>(x, y, out, out_size);
}

// round 8
// speedup vs baseline: 1.3362x; 1.0117x over previous
#include <cuda_runtime.h>
#include <cstdint>
#include <cstring>
#include <vector>
#include <algorithm>

#define B_ROWS 16384
#define D_COLS 2048
#define NCLS   1000

// Scratch (device globals: allocation-free per harness rules)
__device__ unsigned short g_index[B_ROWS];          // permutation, host-computed
__device__ unsigned short g_rows[B_ROWS];           // row ids grouped by class (CSR, unsorted)
__device__ int g_off[NCLS + 1];                     // CSR offsets
__device__ float g_cn[NCLS * D_COLS];               // class_noise matrix (8MB)

// ---------------------------------------------------------------------------
// JAX threefry2x32 (20 rounds), bit-exact. Host+device.
// ---------------------------------------------------------------------------
__host__ __device__ __forceinline__ void threefry2x32(
    uint32_t k0, uint32_t k1, uint32_t x0, uint32_t x1,
    uint32_t &o0, uint32_t &o1)
{
    uint32_t ks0 = k0, ks1 = k1, ks2 = k0 ^ k1 ^ 0x1BD11BDAu;
    x0 += ks0; x1 += ks1;
    const int R[2][4] = {{13, 15, 26, 6}, {17, 29, 16, 24}};
#pragma unroll
    for (int i = 0; i < 5; i++) {
#pragma unroll
        for (int j = 0; j < 4; j++) {
            int r = R[i & 1][j];
            x0 += x1;
            x1 = (x1 << r) | (x1 >> (32 - r));
            x1 ^= x0;
        }
        uint32_t a = (i + 1) % 3 == 0 ? ks0 : ((i + 1) % 3 == 1 ? ks1 : ks2);
        uint32_t b = (i + 2) % 3 == 0 ? ks0 : ((i + 2) % 3 == 1 ? ks1 : ks2);
        x0 += a;
        x1 += b + (uint32_t)(i + 1);
    }
    o0 = x0; o1 = x1;
}

// ---------------------------------------------------------------------------
// XLA f32 ErfInv (Giles polynomial)
// ---------------------------------------------------------------------------
__device__ __forceinline__ float erfinv_f32(float x)
{
    float w = -log1pf(-x * x);
    float p;
    if (w < 5.0f) {
        w -= 2.5f;
        p = 2.81022636e-08f;
        p = fmaf(p, w, 3.43273939e-07f);
        p = fmaf(p, w, -3.5233877e-06f);
        p = fmaf(p, w, -4.39150654e-06f);
        p = fmaf(p, w, 0.00021858087f);
        p = fmaf(p, w, -0.00125372503f);
        p = fmaf(p, w, -0.00417768164f);
        p = fmaf(p, w, 0.246640727f);
        p = fmaf(p, w, 1.50140941f);
    } else {
        w = sqrtf(w) - 3.0f;
        p = -0.000200214257f;
        p = fmaf(p, w, 0.000100950558f);
        p = fmaf(p, w, 0.00134934322f);
        p = fmaf(p, w, -0.00367342844f);
        p = fmaf(p, w, 0.00573950773f);
        p = fmaf(p, w, -0.0076224613f);
        p = fmaf(p, w, 0.00943887047f);
        p = fmaf(p, w, 1.00167406f);
        p = fmaf(p, w, 2.83297682f);
    }
    return p * x;
}

__device__ __forceinline__ float jax_normal(uint32_t nk0, uint32_t nk1, uint32_t idx)
{
    uint32_t b0, b1;
    threefry2x32(nk0, nk1, 0u, idx, b0, b1);
    uint32_t bits = b0 ^ b1;
    float f = __uint_as_float((bits >> 9) | 0x3f800000u);   // [1,2)
    const float lo = -0.99999994039535522461f;               // nextafter(-1,0)
    float u = fmaxf(lo, fmaf(f - 1.0f, 2.0f, lo));
    return 1.41421356237309504880f * erfinv_f32(u);
}

__device__ __forceinline__ float cn_val(float s, float q, float cnt,
                                        uint32_t nk0, uint32_t nk1, uint32_t flat)
{
    float mean = s / cnt;
    float var  = (q - cnt * mean * mean) / (cnt - 1.0f);
    float sd   = sqrtf(fmaxf(var, 0.0f));
    return mean + sd * jax_normal(nk0, nk1, flat);
}

// ---------------------------------------------------------------------------
// Kernel A: build per-class CSR of row indices (sorting done per stats CTA).
// Single CTA, 1024 threads: histogram -> scan -> smem scatter -> write-out.
// ---------------------------------------------------------------------------
__global__ __launch_bounds__(1024) void build_csr_kernel(const int* __restrict__ y)
{
    __shared__ int cnt[1024];
    __shared__ int sc[1024];
    __shared__ int cur[1024];
    __shared__ unsigned short rows_sm[B_ROWS];   // 32KB
    int t = threadIdx.x;
    cnt[t] = 0;
    __syncthreads();
    for (int i = t; i < B_ROWS; i += 1024) atomicAdd(&cnt[y[i]], 1);
    __syncthreads();
    sc[t] = cnt[t];
    __syncthreads();
    for (int d = 1; d < 1024; d <<= 1) {
        int add = (t >= d) ? sc[t - d] : 0;
        __syncthreads();
        sc[t] += add;
        __syncthreads();
    }
    int excl = (t == 0) ? 0 : sc[t - 1];   // exclusive prefix
    cur[t] = excl;
    if (t <= NCLS) g_off[t] = (t == 0) ? 0 : sc[t - 1];
    __syncthreads();
    for (int i = t; i < B_ROWS; i += 1024) {
        int c = y[i];
        int p = atomicAdd(&cur[c], 1);
        rows_sm[p] = (unsigned short)i;
    }
    __syncthreads();
    uint4* dst = reinterpret_cast<uint4*>(g_rows);
    const uint4* src = reinterpret_cast<const uint4*>(rows_sm);
    for (int i = t; i < B_ROWS / 8; i += 1024) dst[i] = src[i];
}

// ---------------------------------------------------------------------------
// Kernel B: per-class stats fused with noise generation.
// grid (NCLS, 4): one CTA per (class, 512-float D-chunk); 128 thr x 1 float4.
// Row list sorted by warp 0 via shfl_xor bitonic (n<=32: zero barriers);
// rare n>32 classes use the CTA odd-even fallback (CTA-uniform branch).
// Scalar accumulation (R6-proven: occ/regs beat packed math here).
// ---------------------------------------------------------------------------
__global__ __launch_bounds__(128) void stats_noise_kernel(
    const float* __restrict__ x, uint32_t nk0, uint32_t nk1)
{
    __shared__ unsigned int offs[128];
    int c = blockIdx.x;
    int t = threadIdx.x;
    int lane = t & 31;
    int beg = __ldg(&g_off[c]);
    int n   = __ldg(&g_off[c + 1]) - beg;
    int nc  = min(n, 128);

    if (n <= 32) {
        if (t < 32) {   // warp 0: register bitonic sort, no barriers
            unsigned int v = (lane < n) ? (unsigned int)g_rows[beg + lane] : 0xFFFFFFFFu;
#pragma unroll
            for (int k = 2; k <= 32; k <<= 1) {
#pragma unroll
                for (int j = k >> 1; j > 0; j >>= 1) {
                    unsigned int p = __shfl_xor_sync(0xFFFFFFFFu, v, j);
                    bool up = ((lane & k) == 0);
                    bool keepMin = (((lane & j) == 0) == up);
                    unsigned int mn = min(v, p), mx = max(v, p);
                    v = keepMin ? mn : mx;
                }
            }
            if (lane < n) offs[lane] = v * D_COLS;
        }
    } else {            // rare straggler classes: CTA odd-even sort in smem
        __shared__ unsigned short rows[128];
        for (int i = t; i < nc; i += 128) rows[i] = g_rows[beg + i];
        __syncthreads();
        for (int ph = 0; ph < nc; ph++) {
            int i = 2 * t + (ph & 1);
            if (i + 1 < nc) {
                unsigned short a = rows[i], b = rows[i + 1];
                if (a > b) { rows[i] = b; rows[i + 1] = a; }
            }
            __syncthreads();
        }
        for (int i = t; i < nc; i += 128) offs[i] = (unsigned int)rows[i] * D_COLS;
    }
    __syncthreads();

    int col = blockIdx.y * 512 + t * 4;                 // float index in row
    const float* xb = x + col;
    float4 s = {0, 0, 0, 0}, q = {0, 0, 0, 0};

#define ACC(V) \
    s.x += V.x; s.y += V.y; s.z += V.z; s.w += V.w; \
    q.x += V.x*V.x; q.y += V.y*V.y; q.z += V.z*V.z; q.w += V.w*V.w;

    int r = 0;
    for (; r + 4 <= n; r += 4) {
        unsigned int o0 = offs[r], o1 = offs[r + 1], o2 = offs[r + 2], o3 = offs[r + 3];
        float4 v0 = *reinterpret_cast<const float4*>(xb + o0);
        float4 v1 = *reinterpret_cast<const float4*>(xb + o1);
        float4 v2 = *reinterpret_cast<const float4*>(xb + o2);
        float4 v3 = *reinterpret_cast<const float4*>(xb + o3);
        ACC(v0) ACC(v1) ACC(v2) ACC(v3)
    }
    for (; r < n; r++) {
        unsigned int oo = (r < 128) ? offs[r] : (unsigned int)g_rows[beg + r] * D_COLS;
        float4 v = *reinterpret_cast<const float4*>(xb + oo);
        ACC(v)
    }
#undef ACC

    float cnt = (float)n;
    uint32_t flat = (uint32_t)c * (uint32_t)D_COLS + (uint32_t)col;
    float4 o;
    o.x = cn_val(s.x, q.x, cnt, nk0, nk1, flat + 0u);
    o.y = cn_val(s.y, q.y, cnt, nk0, nk1, flat + 1u);
    o.z = cn_val(s.z, q.z, cnt, nk0, nk1, flat + 2u);
    o.w = cn_val(s.w, q.w, cnt, nk0, nk1, flat + 3u);
    *reinterpret_cast<float4*>(g_cn + (size_t)c * D_COLS + col) = o;
}

// ---------------------------------------------------------------------------
// Kernel C: out = 0.9*x + 0.1*cn[newY[row]] via packed f32x2 (R7-proven).
// ---------------------------------------------------------------------------
__global__ __launch_bounds__(256) void out_kernel(
    const float* __restrict__ x, const int* __restrict__ y,
    float* __restrict__ out, int out_size)
{
    int row = blockIdx.x;
    int t = threadIdx.x;
    int c = __ldg(&y[g_index[row]]);
    const float4* x4 = reinterpret_cast<const float4*>(x) + (size_t)row * 512;
    const float4* n4 = reinterpret_cast<const float4*>(g_cn) + (size_t)c * 512;
    float4* o4 = reinterpret_cast<float4*>(out) + (size_t)row * 512;

    float4 a0 = __ldcs(x4 + t);
    float4 a1 = __ldcs(x4 + t + 256);
    float4 b0 = __ldg(n4 + t);
    float4 b1 = __ldg(n4 + t + 256);

    const unsigned long long C09 = 0x3f6666663f666666ull;  // {0.9f, 0.9f}
    const unsigned long long C01 = 0x3dcccccd3dcccccdull;  // {0.1f, 0.1f}
#define BLEND(A, O) { \
    ulonglong2 av = *reinterpret_cast<ulonglong2*>(&A); \
    ulonglong2 bv = *reinterpret_cast<ulonglong2*>(&O); \
    unsigned long long r0, r1; \
    asm("mul.rn.f32x2 %0, %1, %2;" : "=l"(r0) : "l"(av.x), "l"(C09)); \
    asm("mul.rn.f32x2 %0, %1, %2;" : "=l"(r1) : "l"(av.y), "l"(C09)); \
    asm("fma.rn.f32x2 %0, %1, %2, %3;" : "=l"(r0) : "l"(bv.x), "l"(C01), "l"(r0)); \
    asm("fma.rn.f32x2 %0, %1, %2, %3;" : "=l"(r1) : "l"(bv.y), "l"(C01), "l"(r1)); \
    av.x = r0; av.y = r1; \
    A = *reinterpret_cast<float4*>(&av); }

    BLEND(a0, b0)
    BLEND(a1, b1)
#undef BLEND
    __stcs(o4 + t, a0);
    __stcs(o4 + t + 256, a1);

    if (t == 0) {
        long long p = (long long)B_ROWS * D_COLS + row;
        if (p < (long long)out_size) out[p] = (float)c;   // newY as numeric value
    }
}

// ---------------------------------------------------------------------------
// Permutation upload via kernel parameters (no memcpy nodes).
// ---------------------------------------------------------------------------
struct IdxChunk { unsigned short v[8192]; };

__global__ void upload_idx_kernel(IdxChunk ch, int off)
{
    int t = blockIdx.x * blockDim.x + threadIdx.x;
    if (t < 8192) g_index[off + t] = ch.v[t];
}

// ---------------------------------------------------------------------------
// Host: jax.random key derivation + permutation (2 stable-sort rounds).
// ---------------------------------------------------------------------------
extern "C" void kernel_launch(void* const* d_in, const int* in_sizes, int n_in,
                              void* d_out, int out_size)
{
    const float* x = (const float*)d_in[0];
    const int*   y = (const int*)d_in[1];
    float* out = (float*)d_out;

    uint32_t nk0, nk1, pk0, pk1;
    threefry2x32(0u, 42u, 0u, 0u, nk0, nk1);
    threefry2x32(0u, 42u, 0u, 1u, pk0, pk1);

    std::vector<uint16_t> perm(B_ROWS), tmp(B_ROWS);
    std::vector<uint64_t> buf(B_ROWS);
    for (int i = 0; i < B_ROWS; i++) perm[i] = (uint16_t)i;
    uint32_t k0 = pk0, k1 = pk1;
    const int NUM_ROUNDS = 2;   // ceil(3*log(16384)/log(2^32-1))
    for (int r = 0; r < NUM_ROUNDS; r++) {
        uint32_t t0, t1, s0, s1;
        threefry2x32(k0, k1, 0u, 0u, t0, t1);
        threefry2x32(k0, k1, 0u, 1u, s0, s1);
        k0 = t0; k1 = t1;
        for (int i = 0; i < B_ROWS; i++) {
            uint32_t b0, b1;
            threefry2x32(s0, s1, 0u, (uint32_t)i, b0, b1);
            buf[i] = ((uint64_t)(b0 ^ b1) << 32) | (uint32_t)i;
        }
        std::sort(buf.begin(), buf.end());
        for (int j = 0; j < B_ROWS; j++)
            tmp[j] = perm[(uint32_t)(buf[j] & 0xFFFFFFFFu)];
        perm.swap(tmp);
    }

    IdxChunk c0, c1;
    memcpy(c0.v, perm.data(),        8192 * sizeof(uint16_t));
    memcpy(c1.v, perm.data() + 8192, 8192 * sizeof(uint16_t));
    upload_idx_kernel<<<32, 256>>>(c0, 0);
    upload_idx_kernel<<<32, 256>>>(c1, 8192);

    build_csr_kernel<<<1, 1024>>>(y);
    dim3 sgrid(NCLS, 4);
    stats_noise_kernel<<<sgrid, 128>>>(x, nk0, nk1);
    out_kernel<<<B_ROWS, 256>>>(x, y, out, out_size);
}